// round 1
// baseline (speedup 1.0000x reference)
#include <cuda_runtime.h>
#include <math.h>

// Petrosian fractal features, 5 scales, T=4096, 57 windows/row.
// One block per (b,c) row. Row loaded once into smem; sign-change
// indicator prefix-summed; each window = 2 prefix lookups.

#define T_LEN 4096
#define THREADS 256
#define PER_THREAD 16   // 4096 / 256
#define N_WIN 57

__global__ __launch_bounds__(THREADS)
void petrosian_kernel(const float* __restrict__ x, float* __restrict__ out, int n_rows) {
    __shared__ float row[T_LEN];
    __shared__ int   pre[T_LEN];
    __shared__ int   warp_sums[8];

    const int bc = blockIdx.x;
    if (bc >= n_rows) return;
    const float* xr = x + (size_t)bc * T_LEN;
    const int tid = threadIdx.x;

    // ---- load row (coalesced float4) ----
    const float4* x4 = (const float4*)xr;
    float4* r4 = (float4*)row;
    #pragma unroll
    for (int i = 0; i < 4; i++)
        r4[tid + i * THREADS] = x4[tid + i * THREADS];
    __syncthreads();

    // ---- indicator + local inclusive scan over 16 consecutive j ----
    // s[j] = (row[j+1]-row[j])*(row[j+2]-row[j+1]) < 0, valid j in [0, T-3]
    int vals[PER_THREAD];
    const int base = tid * PER_THREAD;
    float a  = row[base];
    float b  = row[base + 1];
    float d0 = b - a;
    int local = 0;
    #pragma unroll
    for (int i = 0; i < PER_THREAD; i++) {
        int j = base + i;
        float c_ = (j + 2 < T_LEN) ? row[j + 2] : 0.0f;
        float d1 = c_ - b;
        int s = (j + 2 < T_LEN) && (d0 * d1 < 0.0f);
        local += s;
        vals[i] = local;
        b = c_;
        d0 = d1;
    }

    // ---- warp scan of per-thread totals ----
    const int lane = tid & 31, wid = tid >> 5;
    int scan = local;
    #pragma unroll
    for (int off = 1; off < 32; off <<= 1) {
        int n = __shfl_up_sync(0xffffffffu, scan, off);
        if (lane >= off) scan += n;
    }
    if (lane == 31) warp_sums[wid] = scan;
    __syncthreads();

    // exclusive scan of the 8 warp totals (warp 0, lanes 0..7)
    if (wid == 0 && lane < 8) {
        int v = warp_sums[lane];
        int sc = v;
        #pragma unroll
        for (int off = 1; off < 8; off <<= 1) {
            int n = __shfl_up_sync(0xffu, sc, off);
            if (lane >= off) sc += n;
        }
        warp_sums[lane] = sc - v;   // exclusive
    }
    __syncthreads();

    const int thread_excl = warp_sums[wid] + (scan - local);
    #pragma unroll
    for (int i = 0; i < PER_THREAD; i++)
        pre[base + i] = thread_excl + vals[i];  // inclusive global prefix
    __syncthreads();

    // ---- 57 window outputs: zc = pre[start+w-3] - pre[start-1] ----
    if (tid < N_WIN) {
        int k = tid, w, start;
        if      (k < 1)  { w = 4096; start = 0; }
        else if (k < 4)  { w = 2048; start = (k - 1)  * 1024; }
        else if (k < 11) { w = 1024; start = (k - 4)  * 512;  }
        else if (k < 26) { w = 512;  start = (k - 11) * 256;  }
        else             { w = 256;  start = (k - 26) * 128;  }

        int hi = pre[start + w - 3];
        int lo = (start > 0) ? pre[start - 1] : 0;
        float zc = (float)(hi - lo);

        float wf = (float)w;
        float L = log10f(wf);
        float denom = L + log10f(wf / (wf + 0.4f * zc));
        out[(size_t)bc * N_WIN + k] = L / denom;
    }
}

extern "C" void kernel_launch(void* const* d_in, const int* in_sizes, int n_in,
                              void* d_out, int out_size) {
    const float* x = (const float*)d_in[0];
    float* out = (float*)d_out;
    int n_rows = in_sizes[0] / T_LEN;   // B*C = 4096
    petrosian_kernel<<<n_rows, THREADS>>>(x, out, n_rows);
}